// round 1
// baseline (speedup 1.0000x reference)
#include <cuda_runtime.h>
#include <math.h>

#define N_NODES 50000
#define N_EDGES 400000
#define HID 64
#define F_IN 8
#define NL 3

// padded dims
#define K1 132    // e_in padded (130 -> 132)
#define N1 288    // edge hidden padded (260 -> 288)

// ---------------- device scratch (no allocations allowed) ----------------
__device__ float g_feats[N_NODES * HID];
__device__ float g_coors[N_NODES * 3];
__device__ float g_magg[N_NODES * HID];
__device__ float g_cdelta[N_NODES * 3];
__device__ float g_eW1p[NL * K1 * N1];
__device__ float g_eb1p[NL * N1];
__device__ float g_eW2p[NL * N1 * HID];

__device__ __forceinline__ float silu_f(float v) {
    return v * __fdividef(1.0f, 1.0f + __expf(-v));
}

// ---------------- generic 64-row GEMM tile, 256 threads ----------------
// C[64][N] = act(A[64][K] @ Wg[K][N] + Bg[N])
// A in smem (stride AS), Wg global staged via Wsm chunks of KC rows,
// C to smem (stride CS). Thread (er=tid>>5, cc=tid&31) computes rows
// er*8..er*8+7, cols cc+32*j.
template<int K, int N, int KC, int AS, int CS, bool ACT>
__device__ __forceinline__ void gemm64(const float* __restrict__ A,
                                       const float* __restrict__ Wg,
                                       const float* __restrict__ Bg,
                                       float* __restrict__ C,
                                       float* __restrict__ Wsm)
{
    constexpr int CPT = N / 32;
    const int tid = threadIdx.x;
    const int er = tid >> 5;
    const int cc = tid & 31;

    float acc[8][CPT];
#pragma unroll
    for (int i = 0; i < 8; i++)
#pragma unroll
        for (int j = 0; j < CPT; j++) acc[i][j] = 0.0f;

    for (int k0 = 0; k0 < K; k0 += KC) {
        __syncthreads();
        for (int idx = tid; idx < KC * N; idx += 256)
            Wsm[idx] = Wg[k0 * N + idx];
        __syncthreads();
#pragma unroll
        for (int kk = 0; kk < KC; kk++) {
            float wv[CPT];
#pragma unroll
            for (int j = 0; j < CPT; j++) wv[j] = Wsm[kk * N + cc + 32 * j];
#pragma unroll
            for (int i = 0; i < 8; i++) {
                float a = A[(er * 8 + i) * AS + k0 + kk];
#pragma unroll
                for (int j = 0; j < CPT; j++) acc[i][j] = fmaf(a, wv[j], acc[i][j]);
            }
        }
    }
    __syncthreads();
    float bv[CPT];
#pragma unroll
    for (int j = 0; j < CPT; j++) bv[j] = Bg[cc + 32 * j];
#pragma unroll
    for (int i = 0; i < 8; i++)
#pragma unroll
        for (int j = 0; j < CPT; j++) {
            float v = acc[i][j] + bv[j];
            if (ACT) v = silu_f(v);
            C[(er * 8 + i) * CS + cc + 32 * j] = v;
        }
}

// ---------------- weight padding / prep ----------------
__global__ void __launch_bounds__(256) pad_kernel(const float* __restrict__ eW1,
                                                  const float* __restrict__ eb1,
                                                  const float* __restrict__ eW2)
{
    const int A = NL * K1 * N1;        // eW1p
    const int B = NL * N1;             // eb1p
    const int Cc = NL * N1 * HID;      // eW2p
    int i = blockIdx.x * 256 + threadIdx.x;
    if (i < A) {
        int l = i / (K1 * N1);
        int r = (i / N1) % K1;
        int j = i % N1;
        g_eW1p[i] = (r < 130 && j < 260) ? eW1[(l * 130 + r) * 260 + j] : 0.0f;
    } else if (i < A + B) {
        int ii = i - A;
        int l = ii / N1, j = ii % N1;
        g_eb1p[ii] = (j < 260) ? eb1[l * 260 + j] : 0.0f;
    } else if (i < A + B + Cc) {
        int ii = i - A - B;
        int l = ii / (N1 * HID);
        int r = (ii / HID) % N1;
        int j = ii % HID;
        g_eW2p[ii] = (r < 260) ? eW2[(l * 260 + r) * HID + j] : 0.0f;
    }
}

// ---------------- embed + pos copy ----------------
__global__ void __launch_bounds__(256) embed_kernel(const float* __restrict__ x,
                                                    const float* __restrict__ pos,
                                                    const float* __restrict__ W,
                                                    const float* __restrict__ b)
{
    int idx = blockIdx.x * 256 + threadIdx.x;
    if (idx < N_NODES * 3) g_coors[idx] = pos[idx];
    if (idx < N_NODES * HID) {
        int n = idx >> 6, j = idx & 63;
        float acc = b[j];
#pragma unroll
        for (int k = 0; k < F_IN; k++) acc = fmaf(x[n * F_IN + k], W[k * HID + j], acc);
        g_feats[idx] = acc;
    }
}

// ---------------- per-layer zero of aggregation buffers ----------------
__global__ void __launch_bounds__(256) zero_kernel()
{
    int i = blockIdx.x * 256 + threadIdx.x;
    if (i < N_NODES * HID) g_magg[i] = 0.0f;
    else if (i < N_NODES * HID + N_NODES * 3) g_cdelta[i - N_NODES * HID] = 0.0f;
}

// ---------------- edge kernel ----------------
// smem float layout:
//   R1 [0, 8448)        : e_in (64x132) / m (64x64)
//   R2 [8448, 26880)    : h1 (64x288) / c1 (64x260)
//   Wsm [26880, 30336)  : weight staging (12x288)
//   srow [30336, 30400) : int row idx
//   scol [30400, 30464) : int col idx
//   srel [30464, 30720) : rel (64x4)
//   red  [30720, 30976) : partial dots
#define EDGE_SMEM_F 30976

__global__ void __launch_bounds__(256) edge_kernel(const int* __restrict__ ei,
                                                   const float* __restrict__ eattr,
                                                   const float* __restrict__ eb2,
                                                   const float* __restrict__ cW1,
                                                   const float* __restrict__ cb1,
                                                   const float* __restrict__ cW2,
                                                   const float* __restrict__ cb2,
                                                   int l)
{
    extern __shared__ float sm[];
    float* R1 = sm;
    float* R2 = sm + 8448;
    float* Wsm = sm + 26880;
    int* srow = (int*)(sm + 30336);
    int* scol = (int*)(sm + 30400);
    float* srel = sm + 30464;
    float* red = sm + 30720;

    const int tid = threadIdx.x;
    const int e0 = blockIdx.x * 64;

    // phase 0a: indices, rel, dist, edge_attr
    if (tid < 64) {
        int e = e0 + tid;
        int r = ei[e];
        int c = ei[N_EDGES + e];
        srow[tid] = r;
        scol[tid] = c;
        float rx = g_coors[r * 3 + 0] - g_coors[c * 3 + 0];
        float ry = g_coors[r * 3 + 1] - g_coors[c * 3 + 1];
        float rz = g_coors[r * 3 + 2] - g_coors[c * 3 + 2];
        srel[tid * 4 + 0] = rx;
        srel[tid * 4 + 1] = ry;
        srel[tid * 4 + 2] = rz;
        R1[tid * K1 + 128] = eattr[e];
        R1[tid * K1 + 129] = rx * rx + ry * ry + rz * rz;
        R1[tid * K1 + 130] = 0.0f;
        R1[tid * K1 + 131] = 0.0f;
    }
    __syncthreads();
    // phase 0b: gather feats
    for (int idx = tid; idx < 64 * 64; idx += 256) {
        int e = idx >> 6, k = idx & 63;
        R1[e * K1 + k]      = g_feats[srow[e] * HID + k];
        R1[e * K1 + 64 + k] = g_feats[scol[e] * HID + k];
    }

    // edge MLP
    gemm64<K1, N1, 12, K1, N1, true>(R1, g_eW1p + l * K1 * N1, g_eb1p + l * N1, R2, Wsm);
    gemm64<N1, 64, 12, N1, 64, true>(R2, g_eW2p + l * N1 * HID, eb2 + l * HID, R1, Wsm);
    // coors MLP hidden
    gemm64<64, 256, 8, 64, 260, true>(R1, cW1 + l * 64 * 256, cb1 + l * 256, R2, Wsm);
    __syncthreads();

    // final dot: cw[e] = c1[e] . cW2 + cb2
    {
        int e = tid >> 2, q = tid & 3;
        const float* w2 = cW2 + l * 256;
        float s = 0.0f;
#pragma unroll 8
        for (int kk = 0; kk < 64; kk++)
            s = fmaf(R2[e * 260 + q * 64 + kk], w2[q * 64 + kk], s);
        red[tid] = s;
    }
    __syncthreads();
    if (tid < 64) {
        float cw = red[tid * 4 + 0] + red[tid * 4 + 1] + red[tid * 4 + 2] + red[tid * 4 + 3]
                 + cb2[l];
        int r = srow[tid];
        atomicAdd(&g_cdelta[r * 3 + 0], cw * srel[tid * 4 + 0]);
        atomicAdd(&g_cdelta[r * 3 + 1], cw * srel[tid * 4 + 1]);
        atomicAdd(&g_cdelta[r * 3 + 2], cw * srel[tid * 4 + 2]);
    }
    // scatter m into node aggregation
    for (int idx = tid; idx < 64 * 64; idx += 256) {
        int e = idx >> 6, k = idx & 63;
        atomicAdd(&g_magg[srow[e] * HID + k], R1[e * 64 + k]);
    }
}

// ---------------- node kernel ----------------
// smem: sH [0,8192) (h 64x128; later reused for out 64x64), sT1 [8192,16384), Wsm [16384,18432)
#define NODE_SMEM_F 18432

__global__ void __launch_bounds__(256) node_kernel(const float* __restrict__ nW1,
                                                   const float* __restrict__ nb1,
                                                   const float* __restrict__ nW2,
                                                   const float* __restrict__ nb2,
                                                   int l)
{
    extern __shared__ float sm[];
    float* sH = sm;
    float* sT1 = sm + 8192;
    float* Wsm = sm + 16384;

    const int tid = threadIdx.x;
    const int n0 = blockIdx.x * 64;

    for (int idx = tid; idx < 64 * 64; idx += 256) {
        int nl = idx >> 6, k = idx & 63;
        int n = n0 + nl;
        float f = 0.0f, mg = 0.0f;
        if (n < N_NODES) { f = g_feats[n * HID + k]; mg = g_magg[n * HID + k]; }
        sH[nl * 128 + k] = f;
        sH[nl * 128 + 64 + k] = mg;
    }

    gemm64<128, 128, 16, 128, 128, true>(sH, nW1 + l * 128 * 128, nb1 + l * 128, sT1, Wsm);
    gemm64<128, 64, 16, 128, 64, false>(sT1, nW2 + l * 128 * 64, nb2 + l * 64, sH, Wsm);
    __syncthreads();

    for (int idx = tid; idx < 64 * 64; idx += 256) {
        int nl = idx >> 6, k = idx & 63;
        int n = n0 + nl;
        if (n < N_NODES) g_feats[n * HID + k] += sH[nl * 64 + k];
    }
    if (tid < 192) {
        int n = n0 + tid / 3;
        int d = tid % 3;
        if (n < N_NODES) g_coors[n * 3 + d] += g_cdelta[n * 3 + d];
    }
}

// ---------------- final projection ----------------
__global__ void __launch_bounds__(256) final_kernel(const float* __restrict__ linW,
                                                    const float* __restrict__ linb,
                                                    float* __restrict__ out)
{
    int warp = (blockIdx.x * 256 + threadIdx.x) >> 5;
    int lane = threadIdx.x & 31;
    if (warp >= N_NODES) return;
    const float* f = g_feats + warp * HID;
    float s = fmaf(f[lane], linW[lane], f[lane + 32] * linW[lane + 32]);
#pragma unroll
    for (int o = 16; o > 0; o >>= 1) s += __shfl_xor_sync(0xFFFFFFFFu, s, o);
    if (lane == 0) out[warp] = s + linb[0];
}

// ---------------- launch ----------------
extern "C" void kernel_launch(void* const* d_in, const int* in_sizes, int n_in,
                              void* d_out, int out_size)
{
    const float* x      = (const float*)d_in[0];
    const float* pos    = (const float*)d_in[1];
    const int*   ei     = (const int*)  d_in[2];
    const float* eattr  = (const float*)d_in[3];
    const float* embedW = (const float*)d_in[4];
    const float* embedb = (const float*)d_in[5];
    const float* eW1    = (const float*)d_in[6];
    const float* eb1    = (const float*)d_in[7];
    const float* eW2    = (const float*)d_in[8];
    const float* eb2    = (const float*)d_in[9];
    const float* cW1    = (const float*)d_in[10];
    const float* cb1    = (const float*)d_in[11];
    const float* cW2    = (const float*)d_in[12];
    const float* cb2    = (const float*)d_in[13];
    const float* nW1    = (const float*)d_in[14];
    const float* nb1    = (const float*)d_in[15];
    const float* nW2    = (const float*)d_in[16];
    const float* nb2    = (const float*)d_in[17];
    const float* linW   = (const float*)d_in[18];
    const float* linb   = (const float*)d_in[19];
    float* out = (float*)d_out;

    cudaFuncSetAttribute(edge_kernel, cudaFuncAttributeMaxDynamicSharedMemorySize,
                         EDGE_SMEM_F * 4);
    cudaFuncSetAttribute(node_kernel, cudaFuncAttributeMaxDynamicSharedMemorySize,
                         NODE_SMEM_F * 4);

    {
        int total = NL * K1 * N1 + NL * N1 + NL * N1 * HID;
        pad_kernel<<<(total + 255) / 256, 256>>>(eW1, eb1, eW2);
    }
    embed_kernel<<<(N_NODES * HID + 255) / 256, 256>>>(x, pos, embedW, embedb);

    for (int l = 0; l < NL; l++) {
        int ztotal = N_NODES * HID + N_NODES * 3;
        zero_kernel<<<(ztotal + 255) / 256, 256>>>();
        edge_kernel<<<N_EDGES / 64, 256, EDGE_SMEM_F * 4>>>(ei, eattr, eb2, cW1, cb1,
                                                            cW2, cb2, l);
        node_kernel<<<(N_NODES + 63) / 64, 256, NODE_SMEM_F * 4>>>(nW1, nb1, nW2, nb2, l);
    }
    final_kernel<<<(N_NODES * 32 + 255) / 256, 256>>>(linW, linb, out);
}

// round 2
// speedup vs baseline: 1.4961x; 1.4961x over previous
#include <cuda_runtime.h>
#include <math.h>

#define N_NODES 50000
#define N_EDGES 400000
#define HID 64
#define F_IN 8
#define NL 3

// padded dims
#define K1 132    // e_in padded (130 -> 132)
#define N1 288    // edge hidden padded (260 -> 288)

// ---------------- device scratch (no allocations allowed) ----------------
__device__ float g_feats[N_NODES * HID];
__device__ float g_coors[N_NODES * 3];
__device__ float g_magg[N_NODES * HID];
__device__ float g_cdelta[N_NODES * 3];
__device__ float g_eW1p[NL * K1 * N1];
__device__ float g_eb1p[NL * N1];
__device__ float g_eW2p[NL * N1 * HID];

__device__ __forceinline__ float silu_f(float v) {
    return v * __fdividef(1.0f, 1.0f + __expf(-v));
}

// packed f32x2 helpers (sm_103a FFMA2 path — only reachable via PTX)
__device__ __forceinline__ unsigned long long packdup(float x) {
    unsigned long long r;
    asm("mov.b64 %0, {%1, %1};" : "=l"(r) : "r"(__float_as_uint(x)));
    return r;
}
__device__ __forceinline__ float2 unpackf2(unsigned long long v) {
    unsigned int lo, hi;
    asm("mov.b64 {%0, %1}, %2;" : "=r"(lo), "=r"(hi) : "l"(v));
    return make_float2(__uint_as_float(lo), __uint_as_float(hi));
}
#define FFMA2(acc, a, w) \
    asm("fma.rn.f32x2 %0, %1, %2, %0;" : "+l"(acc) : "l"(a), "l"(w))

// ---------------- generic 64-row GEMM tile, 512 threads ----------------
// C[64][N] = act(A[64][K] @ Wg[K][N] + Bg[N])
// Thread (er=tid>>5, cc=tid&31): rows er*4..er*4+3.
// Column mapping: pair p -> cols (2cc+64p, 2cc+64p+1), p<P.
//                 optional scalar col 64*P+cc when R==1 (N = 64P + 32R).
// Double-buffered weight staging: Wst holds 2 buffers of KC*N floats.
// Caller guarantees a __syncthreads()-equivalent before A is read (the
// preload sync inside covers writes program-ordered before the call).
// No trailing sync after epilogue (next gemm's preload sync covers it).
template<int K, int N, int KC, int AS, int CS, int P, int R, bool ACT>
__device__ __forceinline__ void gemm_tile(const float* __restrict__ A,
                                          const float* __restrict__ Wg,
                                          const float* __restrict__ Bg,
                                          float* __restrict__ C,
                                          float* __restrict__ Wst)
{
    constexpr int NCHUNK = K / KC;
    constexpr int CHSZ = KC * N;
    constexpr int STG = (CHSZ + 511) / 512;
    const int tid = threadIdx.x;
    const int er = tid >> 5;
    const int cc = tid & 31;

    unsigned long long accp[4][P];
    float accs[4];
#pragma unroll
    for (int i = 0; i < 4; i++) {
        accs[i] = 0.0f;
#pragma unroll
        for (int p = 0; p < P; p++) accp[i][p] = 0ULL;
    }

    // preload chunk 0 into buffer 0
    for (int idx = tid; idx < CHSZ; idx += 512) Wst[idx] = Wg[idx];
    __syncthreads();

    for (int c = 0; c < NCHUNK; c++) {
        const float* buf = Wst + (c & 1) * CHSZ;
        float* nbuf = Wst + ((c + 1) & 1) * CHSZ;
        float tmp[STG];
        if (c + 1 < NCHUNK) {
            const float* src = Wg + (c + 1) * CHSZ;
#pragma unroll
            for (int t = 0; t < STG; t++) {
                int idx = tid + t * 512;
                if (idx < CHSZ) tmp[t] = src[idx];
            }
        }
        const int k0 = c * KC;
#pragma unroll
        for (int kk = 0; kk < KC; kk += 2) {
            unsigned long long w0[P], w1[P];
            float ws0 = 0.0f, ws1 = 0.0f;
#pragma unroll
            for (int p = 0; p < P; p++) {
                w0[p] = *(const unsigned long long*)(buf + kk * N + 2 * cc + 64 * p);
                w1[p] = *(const unsigned long long*)(buf + (kk + 1) * N + 2 * cc + 64 * p);
            }
            if (R) {
                ws0 = buf[kk * N + 64 * P + cc];
                ws1 = buf[(kk + 1) * N + 64 * P + cc];
            }
#pragma unroll
            for (int i = 0; i < 4; i++) {
                float2 a2 = *(const float2*)(A + (er * 4 + i) * AS + k0 + kk);
                unsigned long long a0 = packdup(a2.x);
                unsigned long long a1 = packdup(a2.y);
#pragma unroll
                for (int p = 0; p < P; p++) {
                    FFMA2(accp[i][p], a0, w0[p]);
                    FFMA2(accp[i][p], a1, w1[p]);
                }
                if (R) accs[i] = fmaf(a2.y, ws1, fmaf(a2.x, ws0, accs[i]));
            }
        }
        if (c + 1 < NCHUNK) {
#pragma unroll
            for (int t = 0; t < STG; t++) {
                int idx = tid + t * 512;
                if (idx < CHSZ) nbuf[idx] = tmp[t];
            }
        }
        __syncthreads();
    }

    // epilogue: bias + activation + store
    float2 bv[P];
    float bs = 0.0f;
#pragma unroll
    for (int p = 0; p < P; p++) bv[p] = *(const float2*)(Bg + 2 * cc + 64 * p);
    if (R) bs = Bg[64 * P + cc];
#pragma unroll
    for (int i = 0; i < 4; i++) {
#pragma unroll
        for (int p = 0; p < P; p++) {
            float2 v = unpackf2(accp[i][p]);
            v.x += bv[p].x;
            v.y += bv[p].y;
            if (ACT) { v.x = silu_f(v.x); v.y = silu_f(v.y); }
            *(float2*)(C + (er * 4 + i) * CS + 2 * cc + 64 * p) = v;
        }
        if (R) {
            float v = accs[i] + bs;
            if (ACT) v = silu_f(v);
            C[(er * 4 + i) * CS + 64 * P + cc] = v;
        }
    }
}

// ---------------- weight padding / prep ----------------
__global__ void __launch_bounds__(256) pad_kernel(const float* __restrict__ eW1,
                                                  const float* __restrict__ eb1,
                                                  const float* __restrict__ eW2)
{
    const int A = NL * K1 * N1;
    const int B = NL * N1;
    const int Cc = NL * N1 * HID;
    int i = blockIdx.x * 256 + threadIdx.x;
    if (i < A) {
        int l = i / (K1 * N1);
        int r = (i / N1) % K1;
        int j = i % N1;
        g_eW1p[i] = (r < 130 && j < 260) ? eW1[(l * 130 + r) * 260 + j] : 0.0f;
    } else if (i < A + B) {
        int ii = i - A;
        int l = ii / N1, j = ii % N1;
        g_eb1p[ii] = (j < 260) ? eb1[l * 260 + j] : 0.0f;
    } else if (i < A + B + Cc) {
        int ii = i - A - B;
        int l = ii / (N1 * HID);
        int r = (ii / HID) % N1;
        int j = ii % HID;
        g_eW2p[ii] = (r < 260) ? eW2[(l * 260 + r) * HID + j] : 0.0f;
    }
}

// ---------------- embed + pos copy ----------------
__global__ void __launch_bounds__(256) embed_kernel(const float* __restrict__ x,
                                                    const float* __restrict__ pos,
                                                    const float* __restrict__ W,
                                                    const float* __restrict__ b)
{
    int idx = blockIdx.x * 256 + threadIdx.x;
    if (idx < N_NODES * 3) g_coors[idx] = pos[idx];
    if (idx < N_NODES * HID) {
        int n = idx >> 6, j = idx & 63;
        float acc = b[j];
#pragma unroll
        for (int k = 0; k < F_IN; k++) acc = fmaf(x[n * F_IN + k], W[k * HID + j], acc);
        g_feats[idx] = acc;
    }
}

// ---------------- per-layer zero of aggregation buffers ----------------
__global__ void __launch_bounds__(256) zero_kernel()
{
    int i = blockIdx.x * 256 + threadIdx.x;
    if (i < N_NODES * HID) g_magg[i] = 0.0f;
    else if (i < N_NODES * HID + N_NODES * 3) g_cdelta[i - N_NODES * HID] = 0.0f;
}

// ---------------- edge kernel ----------------
// smem float layout:
//   R1   [0, 8448)        : e_in (64x132) / m (64x64)
//   R2   [8448, 26880)    : h1 (64x288) / c1 (64x264, padded stride)
//   Wst  [26880, 33792)   : double-buffered weight staging (2 x 3456)
//   srow [33792, 33856)   : int row idx
//   scol [33856, 33920)   : int col idx
//   srel [33920, 34176)   : rel (64x4)
//   sdot [34176, 34432)   : cW2 (256)
#define EDGE_SMEM_F 34432

__global__ void __launch_bounds__(512) edge_kernel(const int* __restrict__ ei,
                                                   const float* __restrict__ eattr,
                                                   const float* __restrict__ eb2,
                                                   const float* __restrict__ cW1,
                                                   const float* __restrict__ cb1,
                                                   const float* __restrict__ cW2,
                                                   const float* __restrict__ cb2,
                                                   int l)
{
    extern __shared__ float sm[];
    float* R1 = sm;
    float* R2 = sm + 8448;
    float* Wst = sm + 26880;
    int* srow = (int*)(sm + 33792);
    int* scol = (int*)(sm + 33856);
    float* srel = sm + 33920;
    float* sdot = sm + 34176;

    const int tid = threadIdx.x;
    const int e0 = blockIdx.x * 64;

    // phase 0a: indices, rel, dist, edge_attr, dot weights
    if (tid < 256) sdot[tid] = cW2[l * 256 + tid];
    if (tid < 64) {
        int e = e0 + tid;
        int r = ei[e];
        int c = ei[N_EDGES + e];
        srow[tid] = r;
        scol[tid] = c;
        float rx = g_coors[r * 3 + 0] - g_coors[c * 3 + 0];
        float ry = g_coors[r * 3 + 1] - g_coors[c * 3 + 1];
        float rz = g_coors[r * 3 + 2] - g_coors[c * 3 + 2];
        srel[tid * 4 + 0] = rx;
        srel[tid * 4 + 1] = ry;
        srel[tid * 4 + 2] = rz;
        R1[tid * K1 + 128] = eattr[e];
        R1[tid * K1 + 129] = rx * rx + ry * ry + rz * rz;
        R1[tid * K1 + 130] = 0.0f;
        R1[tid * K1 + 131] = 0.0f;
    }
    __syncthreads();
    // phase 0b: gather feats
    for (int idx = tid; idx < 64 * 64; idx += 512) {
        int e = idx >> 6, k = idx & 63;
        R1[e * K1 + k]      = g_feats[srow[e] * HID + k];
        R1[e * K1 + 64 + k] = g_feats[scol[e] * HID + k];
    }

    // edge MLP (gather->sync covered by gemm's preload sync)
    gemm_tile<K1, N1, 12, K1, N1, 4, 1, true>(R1, g_eW1p + l * K1 * N1,
                                              g_eb1p + l * N1, R2, Wst);
    gemm_tile<N1, 64, 32, N1, 64, 1, 0, true>(R2, g_eW2p + l * N1 * HID,
                                              eb2 + l * HID, R1, Wst);
    // coors MLP hidden (output stride 264 for conflict-free dot phase)
    gemm_tile<64, 256, 8, 64, 264, 4, 0, true>(R1, cW1 + l * 64 * 256,
                                               cb1 + l * 256, R2, Wst);
    __syncthreads();

    // dot: cw[e] = c1[e] . cW2 + cb2; lane->bank = 8*(e%4)+q (conflict-free)
    {
        int e = tid >> 3, q = tid & 7;
        float s = 0.0f;
#pragma unroll
        for (int t = 0; t < 32; t++)
            s = fmaf(R2[e * 264 + q + 8 * t], sdot[q + 8 * t], s);
        s += __shfl_xor_sync(0xFFFFFFFFu, s, 1);
        s += __shfl_xor_sync(0xFFFFFFFFu, s, 2);
        s += __shfl_xor_sync(0xFFFFFFFFu, s, 4);
        if (q == 0) {
            float cw = s + cb2[l];
            int r = srow[e];
            atomicAdd(&g_cdelta[r * 3 + 0], cw * srel[e * 4 + 0]);
            atomicAdd(&g_cdelta[r * 3 + 1], cw * srel[e * 4 + 1]);
            atomicAdd(&g_cdelta[r * 3 + 2], cw * srel[e * 4 + 2]);
        }
    }
    // scatter m into node aggregation
    for (int idx = tid; idx < 64 * 64; idx += 512) {
        int e = idx >> 6, k = idx & 63;
        atomicAdd(&g_magg[srow[e] * HID + k], R1[e * 64 + k]);
    }
}

// ---------------- node kernel ----------------
// smem: sH [0,8192), sT1 [8192,16384), Wst [16384,20480)
#define NODE_SMEM_F 20480

__global__ void __launch_bounds__(512) node_kernel(const float* __restrict__ nW1,
                                                   const float* __restrict__ nb1,
                                                   const float* __restrict__ nW2,
                                                   const float* __restrict__ nb2,
                                                   int l)
{
    extern __shared__ float sm[];
    float* sH = sm;
    float* sT1 = sm + 8192;
    float* Wst = sm + 16384;

    const int tid = threadIdx.x;
    const int n0 = blockIdx.x * 64;

    for (int idx = tid; idx < 64 * 64; idx += 512) {
        int nl = idx >> 6, k = idx & 63;
        int n = n0 + nl;
        float f = 0.0f, mg = 0.0f;
        if (n < N_NODES) { f = g_feats[n * HID + k]; mg = g_magg[n * HID + k]; }
        sH[nl * 128 + k] = f;
        sH[nl * 128 + 64 + k] = mg;
    }

    gemm_tile<128, 128, 16, 128, 128, 2, 0, true>(sH, nW1 + l * 128 * 128,
                                                  nb1 + l * 128, sT1, Wst);
    gemm_tile<128, 64, 32, 128, 64, 1, 0, false>(sT1, nW2 + l * 128 * 64,
                                                 nb2 + l * 64, sH, Wst);
    __syncthreads();

    for (int idx = tid; idx < 64 * 64; idx += 512) {
        int nl = idx >> 6, k = idx & 63;
        int n = n0 + nl;
        if (n < N_NODES) g_feats[n * HID + k] += sH[nl * 64 + k];
    }
    if (tid < 192) {
        int n = n0 + tid / 3;
        int d = tid % 3;
        if (n < N_NODES) g_coors[n * 3 + d] += g_cdelta[n * 3 + d];
    }
}

// ---------------- final projection ----------------
__global__ void __launch_bounds__(256) final_kernel(const float* __restrict__ linW,
                                                    const float* __restrict__ linb,
                                                    float* __restrict__ out)
{
    int warp = (blockIdx.x * 256 + threadIdx.x) >> 5;
    int lane = threadIdx.x & 31;
    if (warp >= N_NODES) return;
    const float* f = g_feats + warp * HID;
    float s = fmaf(f[lane], linW[lane], f[lane + 32] * linW[lane + 32]);
#pragma unroll
    for (int o = 16; o > 0; o >>= 1) s += __shfl_xor_sync(0xFFFFFFFFu, s, o);
    if (lane == 0) out[warp] = s + linb[0];
}

// ---------------- launch ----------------
extern "C" void kernel_launch(void* const* d_in, const int* in_sizes, int n_in,
                              void* d_out, int out_size)
{
    const float* x      = (const float*)d_in[0];
    const float* pos    = (const float*)d_in[1];
    const int*   ei     = (const int*)  d_in[2];
    const float* eattr  = (const float*)d_in[3];
    const float* embedW = (const float*)d_in[4];
    const float* embedb = (const float*)d_in[5];
    const float* eW1    = (const float*)d_in[6];
    const float* eb1    = (const float*)d_in[7];
    const float* eW2    = (const float*)d_in[8];
    const float* eb2    = (const float*)d_in[9];
    const float* cW1    = (const float*)d_in[10];
    const float* cb1    = (const float*)d_in[11];
    const float* cW2    = (const float*)d_in[12];
    const float* cb2    = (const float*)d_in[13];
    const float* nW1    = (const float*)d_in[14];
    const float* nb1    = (const float*)d_in[15];
    const float* nW2    = (const float*)d_in[16];
    const float* nb2    = (const float*)d_in[17];
    const float* linW   = (const float*)d_in[18];
    const float* linb   = (const float*)d_in[19];
    float* out = (float*)d_out;

    cudaFuncSetAttribute(edge_kernel, cudaFuncAttributeMaxDynamicSharedMemorySize,
                         EDGE_SMEM_F * 4);
    cudaFuncSetAttribute(node_kernel, cudaFuncAttributeMaxDynamicSharedMemorySize,
                         NODE_SMEM_F * 4);

    {
        int total = NL * K1 * N1 + NL * N1 + NL * N1 * HID;
        pad_kernel<<<(total + 255) / 256, 256>>>(eW1, eb1, eW2);
    }
    embed_kernel<<<(N_NODES * HID + 255) / 256, 256>>>(x, pos, embedW, embedb);

    for (int l = 0; l < NL; l++) {
        int ztotal = N_NODES * HID + N_NODES * 3;
        zero_kernel<<<(ztotal + 255) / 256, 256>>>();
        edge_kernel<<<N_EDGES / 64, 512, EDGE_SMEM_F * 4>>>(ei, eattr, eb2, cW1, cb1,
                                                            cW2, cb2, l);
        node_kernel<<<(N_NODES + 63) / 64, 512, NODE_SMEM_F * 4>>>(nW1, nb1, nW2, nb2, l);
    }
    final_kernel<<<(N_NODES * 32 + 255) / 256, 256>>>(linW, linb, out);
}

// round 3
// speedup vs baseline: 1.7607x; 1.1768x over previous
#include <cuda_runtime.h>
#include <math.h>

#define N_NODES 50000
#define N_EDGES 400000
#define HID 64
#define F_IN 8
#define NL 3

// padded dims
#define K1 132    // e_in padded (130 -> 132)
#define N1 288    // edge hidden padded (260 -> 288)
#define K2 260    // GEMM2 true K (eW2 used unpadded)

#define ETILE 48  // edges per block
#define TPB 256

// ---------------- device scratch (no allocations allowed) ----------------
__device__ float g_feats[N_NODES * HID];
__device__ float g_coors[N_NODES * 3];
__device__ float g_magg[N_NODES * HID];
__device__ float g_cdelta[N_NODES * 3];
__device__ float g_eW1p[NL * K1 * N1];
__device__ float g_eb1p[NL * N1];

__device__ __forceinline__ float silu_f(float v) {
    return v * __fdividef(1.0f, 1.0f + __expf(-v));
}

// packed f32x2 helpers (sm_103a FFMA2 path — only reachable via PTX)
typedef unsigned long long u64;
__device__ __forceinline__ u64 packdup(float x) {
    u64 r;
    asm("mov.b64 %0, {%1, %1};" : "=l"(r) : "r"(__float_as_uint(x)));
    return r;
}
__device__ __forceinline__ float2 unpackf2(u64 v) {
    unsigned int lo, hi;
    asm("mov.b64 {%0, %1}, %2;" : "=r"(lo), "=r"(hi) : "l"(v));
    return make_float2(__uint_as_float(lo), __uint_as_float(hi));
}
#define FFMA2(acc, a, w) \
    asm("fma.rn.f32x2 %0, %1, %2, %0;" : "+l"(acc) : "l"(a), "l"(w))

// ---------------- GEMM tile, 256 threads, RPT rows/thread ----------------
// C[8*RPT][N] = act(A[8*RPT][K] @ Wg[K][N] + Bg[N])
// Thread (er=tid>>5 in 0..7, cc=tid&31): rows er*RPT..er*RPT+RPT-1.
// Cols: pair p -> (2cc+64p, 2cc+64p+1), p<P; scalar col 64P+cc if R==1.
// Wg staged through Wst (double-buffered, KC rows/chunk) with register
// prefetch of the next chunk; W smem reads software-pipelined by one k-pair.
// Preload sync covers A writes program-ordered before the call; no trailing
// sync (next gemm's preload sync, or an explicit one, covers the epilogue).
template<int K, int N, int KC, int AS, int CS, int P, int R, bool ACT, int RPT>
__device__ __forceinline__ void gemm_tile(const float* __restrict__ A,
                                          const float* __restrict__ Wg,
                                          const float* __restrict__ Bg,
                                          float* __restrict__ C,
                                          float* __restrict__ Wst)
{
    constexpr int NCHUNK = K / KC;
    constexpr int CHSZ = KC * N;
    constexpr int STG = (CHSZ + TPB - 1) / TPB;
    const int tid = threadIdx.x;
    const int er = tid >> 5;
    const int cc = tid & 31;

    u64 accp[RPT][P];
    float accs[RPT];
#pragma unroll
    for (int i = 0; i < RPT; i++) {
        accs[i] = 0.0f;
#pragma unroll
        for (int p = 0; p < P; p++) accp[i][p] = 0ULL;
    }

    // preload chunk 0 into buffer 0
    for (int idx = tid; idx < CHSZ; idx += TPB) Wst[idx] = Wg[idx];
    __syncthreads();

    for (int c = 0; c < NCHUNK; c++) {
        const float* buf = Wst + (c & 1) * CHSZ;
        float* nbuf = Wst + ((c + 1) & 1) * CHSZ;
        float tmp[STG];
        if (c + 1 < NCHUNK) {
            const float* src = Wg + (c + 1) * CHSZ;
#pragma unroll
            for (int t = 0; t < STG; t++) {
                int idx = tid + t * TPB;
                if (idx < CHSZ) tmp[t] = src[idx];
            }
        }
        const int k0 = c * KC;

        // register-pipelined W reads (one k-pair ahead)
        u64 w0[P], w1[P];
        float ws0 = 0.0f, ws1 = 0.0f;
#pragma unroll
        for (int p = 0; p < P; p++) {
            w0[p] = *(const u64*)(buf + 0 * N + 2 * cc + 64 * p);
            w1[p] = *(const u64*)(buf + 1 * N + 2 * cc + 64 * p);
        }
        if (R) { ws0 = buf[64 * P + cc]; ws1 = buf[N + 64 * P + cc]; }

#pragma unroll
        for (int kk = 0; kk < KC; kk += 2) {
            u64 nw0[P], nw1[P];
            float nws0 = 0.0f, nws1 = 0.0f;
            if (kk + 2 < KC) {
#pragma unroll
                for (int p = 0; p < P; p++) {
                    nw0[p] = *(const u64*)(buf + (kk + 2) * N + 2 * cc + 64 * p);
                    nw1[p] = *(const u64*)(buf + (kk + 3) * N + 2 * cc + 64 * p);
                }
                if (R) {
                    nws0 = buf[(kk + 2) * N + 64 * P + cc];
                    nws1 = buf[(kk + 3) * N + 64 * P + cc];
                }
            }
#pragma unroll
            for (int i = 0; i < RPT; i++) {
                float2 a2 = *(const float2*)(A + (er * RPT + i) * AS + k0 + kk);
                u64 a0 = packdup(a2.x);
                u64 a1 = packdup(a2.y);
#pragma unroll
                for (int p = 0; p < P; p++) {
                    FFMA2(accp[i][p], a0, w0[p]);
                    FFMA2(accp[i][p], a1, w1[p]);
                }
                if (R) accs[i] = fmaf(a2.y, ws1, fmaf(a2.x, ws0, accs[i]));
            }
#pragma unroll
            for (int p = 0; p < P; p++) { w0[p] = nw0[p]; w1[p] = nw1[p]; }
            if (R) { ws0 = nws0; ws1 = nws1; }
        }
        if (c + 1 < NCHUNK) {
#pragma unroll
            for (int t = 0; t < STG; t++) {
                int idx = tid + t * TPB;
                if (idx < CHSZ) nbuf[idx] = tmp[t];
            }
        }
        __syncthreads();
    }

    // epilogue: bias + activation + store
    float2 bv[P];
    float bs = 0.0f;
#pragma unroll
    for (int p = 0; p < P; p++) bv[p] = *(const float2*)(Bg + 2 * cc + 64 * p);
    if (R) bs = Bg[64 * P + cc];
#pragma unroll
    for (int i = 0; i < RPT; i++) {
#pragma unroll
        for (int p = 0; p < P; p++) {
            float2 v = unpackf2(accp[i][p]);
            v.x += bv[p].x;
            v.y += bv[p].y;
            if (ACT) { v.x = silu_f(v.x); v.y = silu_f(v.y); }
            *(float2*)(C + (er * RPT + i) * CS + 2 * cc + 64 * p) = v;
        }
        if (R) {
            float v = accs[i] + bs;
            if (ACT) v = silu_f(v);
            C[(er * RPT + i) * CS + 64 * P + cc] = v;
        }
    }
}

// ---------------- weight padding / prep (eW1 only) ----------------
__global__ void __launch_bounds__(256) pad_kernel(const float* __restrict__ eW1,
                                                  const float* __restrict__ eb1)
{
    const int A = NL * K1 * N1;
    const int B = NL * N1;
    int i = blockIdx.x * 256 + threadIdx.x;
    if (i < A) {
        int l = i / (K1 * N1);
        int r = (i / N1) % K1;
        int j = i % N1;
        g_eW1p[i] = (r < 130 && j < 260) ? eW1[(l * 130 + r) * 260 + j] : 0.0f;
    } else if (i < A + B) {
        int ii = i - A;
        int l = ii / N1, j = ii % N1;
        g_eb1p[ii] = (j < 260) ? eb1[l * 260 + j] : 0.0f;
    }
}

// ---------------- embed + pos copy ----------------
__global__ void __launch_bounds__(256) embed_kernel(const float* __restrict__ x,
                                                    const float* __restrict__ pos,
                                                    const float* __restrict__ W,
                                                    const float* __restrict__ b)
{
    int idx = blockIdx.x * 256 + threadIdx.x;
    if (idx < N_NODES * 3) g_coors[idx] = pos[idx];
    if (idx < N_NODES * HID) {
        int n = idx >> 6, j = idx & 63;
        float acc = b[j];
#pragma unroll
        for (int k = 0; k < F_IN; k++) acc = fmaf(x[n * F_IN + k], W[k * HID + j], acc);
        g_feats[idx] = acc;
    }
}

// ---------------- per-layer zero of aggregation buffers ----------------
__global__ void __launch_bounds__(256) zero_kernel()
{
    int i = blockIdx.x * 256 + threadIdx.x;
    if (i < N_NODES * HID) g_magg[i] = 0.0f;
    else if (i < N_NODES * HID + N_NODES * 3) g_cdelta[i - N_NODES * HID] = 0.0f;
}

// ---------------- edge kernel (48 edges/block, 256 threads, 2 CTA/SM) -----
// smem float layout:
//   R1   [0, 6336)        : e_in (48x132) / m (48x64)
//   R2   [6336, 20160)    : h1 (48x288) / c1 (48x264 padded stride)
//   Wst  [20160, 27072)   : double-buffered weight staging (2 x 3456 max)
//   srow [27072, 27120)   : int row idx
//   scol [27120, 27168)   : int col idx
//   srel [27168, 27360)   : rel (48x4)
//   sdot [27360, 27616)   : cW2 (256)
#define EDGE_SMEM_F 27616

__global__ void __launch_bounds__(256, 2) edge_kernel(const int* __restrict__ ei,
                                                      const float* __restrict__ eattr,
                                                      const float* __restrict__ eW2,
                                                      const float* __restrict__ eb2,
                                                      const float* __restrict__ cW1,
                                                      const float* __restrict__ cb1,
                                                      const float* __restrict__ cW2,
                                                      const float* __restrict__ cb2,
                                                      int l)
{
    extern __shared__ float sm[];
    float* R1 = sm;
    float* R2 = sm + 6336;
    float* Wst = sm + 20160;
    int* srow = (int*)(sm + 27072);
    int* scol = (int*)(sm + 27120);
    float* srel = sm + 27168;
    float* sdot = sm + 27360;

    const int tid = threadIdx.x;
    const int e0 = blockIdx.x * ETILE;

    // phase 0a: indices, rel, dist, edge_attr, dot weights
    sdot[tid] = cW2[l * 256 + tid];
    if (tid < ETILE) {
        int e = e0 + tid;
        int r = 0, c = 0;
        float ea = 0.0f;
        if (e < N_EDGES) {
            r = ei[e];
            c = ei[N_EDGES + e];
            ea = eattr[e];
        }
        srow[tid] = r;
        scol[tid] = c;
        float rx = g_coors[r * 3 + 0] - g_coors[c * 3 + 0];
        float ry = g_coors[r * 3 + 1] - g_coors[c * 3 + 1];
        float rz = g_coors[r * 3 + 2] - g_coors[c * 3 + 2];
        srel[tid * 4 + 0] = rx;
        srel[tid * 4 + 1] = ry;
        srel[tid * 4 + 2] = rz;
        R1[tid * K1 + 128] = ea;
        R1[tid * K1 + 129] = rx * rx + ry * ry + rz * rz;
        R1[tid * K1 + 130] = 0.0f;
        R1[tid * K1 + 131] = 0.0f;
    }
    __syncthreads();
    // phase 0b: gather feats
    for (int idx = tid; idx < ETILE * 64; idx += TPB) {
        int e = idx >> 6, k = idx & 63;
        R1[e * K1 + k]      = g_feats[srow[e] * HID + k];
        R1[e * K1 + 64 + k] = g_feats[scol[e] * HID + k];
    }

    // edge MLP (gather->sync covered by gemm's preload sync)
    gemm_tile<K1, N1, 12, K1, N1, 4, 1, true, 6>(R1, g_eW1p + l * K1 * N1,
                                                 g_eb1p + l * N1, R2, Wst);
    gemm_tile<K2, 64, 10, N1, 64, 1, 0, true, 6>(R2, eW2 + l * K2 * HID,
                                                 eb2 + l * HID, R1, Wst);
    // coors MLP hidden (output stride 264)
    gemm_tile<64, 256, 8, 64, 264, 4, 0, true, 6>(R1, cW1 + l * 64 * 256,
                                                  cb1 + l * 256, R2, Wst);
    __syncthreads();

    // dot: cw[e] = c1[e] . cW2 + cb2 (4 lanes per edge)
    if (tid < ETILE * 4) {
        int e = tid >> 2, q = tid & 3;
        float s = 0.0f;
#pragma unroll
        for (int t = 0; t < 64; t++)
            s = fmaf(R2[e * 264 + q + 4 * t], sdot[q + 4 * t], s);
        s += __shfl_xor_sync(0xFFFFFFFFu, s, 1);
        s += __shfl_xor_sync(0xFFFFFFFFu, s, 2);
        if (q == 0 && e0 + e < N_EDGES) {
            float cw = s + cb2[l];
            int r = srow[e];
            atomicAdd(&g_cdelta[r * 3 + 0], cw * srel[e * 4 + 0]);
            atomicAdd(&g_cdelta[r * 3 + 1], cw * srel[e * 4 + 1]);
            atomicAdd(&g_cdelta[r * 3 + 2], cw * srel[e * 4 + 2]);
        }
    }
    // scatter m into node aggregation
    for (int idx = tid; idx < ETILE * 64; idx += TPB) {
        int e = idx >> 6, k = idx & 63;
        if (e0 + e < N_EDGES)
            atomicAdd(&g_magg[srow[e] * HID + k], R1[e * 64 + k]);
    }
}

// ---------------- node kernel (64 nodes/block, 256 threads) ----------------
// smem: sH [0,8192), sT1 [8192,16384), Wst [16384,20480)
#define NODE_SMEM_F 20480

__global__ void __launch_bounds__(256, 2) node_kernel(const float* __restrict__ nW1,
                                                      const float* __restrict__ nb1,
                                                      const float* __restrict__ nW2,
                                                      const float* __restrict__ nb2,
                                                      int l)
{
    extern __shared__ float sm[];
    float* sH = sm;
    float* sT1 = sm + 8192;
    float* Wst = sm + 16384;

    const int tid = threadIdx.x;
    const int n0 = blockIdx.x * 64;

    for (int idx = tid; idx < 64 * 64; idx += TPB) {
        int nl = idx >> 6, k = idx & 63;
        int n = n0 + nl;
        float f = 0.0f, mg = 0.0f;
        if (n < N_NODES) { f = g_feats[n * HID + k]; mg = g_magg[n * HID + k]; }
        sH[nl * 128 + k] = f;
        sH[nl * 128 + 64 + k] = mg;
    }

    gemm_tile<128, 128, 16, 128, 128, 2, 0, true, 8>(sH, nW1 + l * 128 * 128,
                                                     nb1 + l * 128, sT1, Wst);
    gemm_tile<128, 64, 16, 128, 64, 1, 0, false, 8>(sT1, nW2 + l * 128 * 64,
                                                    nb2 + l * 64, sH, Wst);
    __syncthreads();

    for (int idx = tid; idx < 64 * 64; idx += TPB) {
        int nl = idx >> 6, k = idx & 63;
        int n = n0 + nl;
        if (n < N_NODES) g_feats[n * HID + k] += sH[nl * 64 + k];
    }
    if (tid < 192) {
        int n = n0 + tid / 3;
        int d = tid % 3;
        if (n < N_NODES) g_coors[n * 3 + d] += g_cdelta[n * 3 + d];
    }
}

// ---------------- final projection ----------------
__global__ void __launch_bounds__(256) final_kernel(const float* __restrict__ linW,
                                                    const float* __restrict__ linb,
                                                    float* __restrict__ out)
{
    int warp = (blockIdx.x * 256 + threadIdx.x) >> 5;
    int lane = threadIdx.x & 31;
    if (warp >= N_NODES) return;
    const float* f = g_feats + warp * HID;
    float s = fmaf(f[lane], linW[lane], f[lane + 32] * linW[lane + 32]);
#pragma unroll
    for (int o = 16; o > 0; o >>= 1) s += __shfl_xor_sync(0xFFFFFFFFu, s, o);
    if (lane == 0) out[warp] = s + linb[0];
}

// ---------------- launch ----------------
extern "C" void kernel_launch(void* const* d_in, const int* in_sizes, int n_in,
                              void* d_out, int out_size)
{
    const float* x      = (const float*)d_in[0];
    const float* pos    = (const float*)d_in[1];
    const int*   ei     = (const int*)  d_in[2];
    const float* eattr  = (const float*)d_in[3];
    const float* embedW = (const float*)d_in[4];
    const float* embedb = (const float*)d_in[5];
    const float* eW1    = (const float*)d_in[6];
    const float* eb1    = (const float*)d_in[7];
    const float* eW2    = (const float*)d_in[8];
    const float* eb2    = (const float*)d_in[9];
    const float* cW1    = (const float*)d_in[10];
    const float* cb1    = (const float*)d_in[11];
    const float* cW2    = (const float*)d_in[12];
    const float* cb2    = (const float*)d_in[13];
    const float* nW1    = (const float*)d_in[14];
    const float* nb1    = (const float*)d_in[15];
    const float* nW2    = (const float*)d_in[16];
    const float* nb2    = (const float*)d_in[17];
    const float* linW   = (const float*)d_in[18];
    const float* linb   = (const float*)d_in[19];
    float* out = (float*)d_out;

    cudaFuncSetAttribute(edge_kernel, cudaFuncAttributeMaxDynamicSharedMemorySize,
                         EDGE_SMEM_F * 4);
    cudaFuncSetAttribute(node_kernel, cudaFuncAttributeMaxDynamicSharedMemorySize,
                         NODE_SMEM_F * 4);

    {
        int total = NL * K1 * N1 + NL * N1;
        pad_kernel<<<(total + 255) / 256, 256>>>(eW1, eb1);
    }
    embed_kernel<<<(N_NODES * HID + 255) / 256, 256>>>(x, pos, embedW, embedb);

    const int egrid = (N_EDGES + ETILE - 1) / ETILE;
    for (int l = 0; l < NL; l++) {
        int ztotal = N_NODES * HID + N_NODES * 3;
        zero_kernel<<<(ztotal + 255) / 256, 256>>>();
        edge_kernel<<<egrid, TPB, EDGE_SMEM_F * 4>>>(ei, eattr, eW2, eb2, cW1, cb1,
                                                     cW2, cb2, l);
        node_kernel<<<(N_NODES + 63) / 64, TPB, NODE_SMEM_F * 4>>>(nW1, nb1, nW2, nb2, l);
    }
    final_kernel<<<(N_NODES * 32 + 255) / 256, 256>>>(linW, linb, out);
}

// round 4
// speedup vs baseline: 2.3711x; 1.3467x over previous
#include <cuda_runtime.h>
#include <math.h>

#define N_NODES 50000
#define N_EDGES 400000
#define HID 64
#define F_IN 8
#define NL 3

// padded dims
#define K1 132    // e_in padded (130 -> 132)
#define N1 288    // edge hidden padded (260 -> 288)
#define K2 260    // GEMM2 true K (eW2 used unpadded)
#define NPAD 50048

#define ETILE 48  // edges per block
#define TPB 256

// ---------------- device scratch (no allocations allowed) ----------------
__device__ float g_feats[N_NODES * HID];
__device__ float g_coors[N_NODES * 3];
__device__ float g_magg[N_NODES * HID];
__device__ float g_cdelta[N_NODES * 3];
__device__ float g_eW1p[NL * K1 * N1];
__device__ float g_eb1p[NL * N1];
__device__ float g_PA[NPAD * N1];   // feats @ W1a + b1 (per current layer)
__device__ float g_PB[NPAD * N1];   // feats @ W1b
__device__ float g_zbias[N1];       // stays zero (device globals zero-init)

__device__ __forceinline__ float silu_f(float v) {
    return v * __fdividef(1.0f, 1.0f + __expf(-v));
}

// packed f32x2 helpers (sm_103a FFMA2 path — only reachable via PTX)
typedef unsigned long long u64;
__device__ __forceinline__ u64 packdup(float x) {
    u64 r;
    asm("mov.b64 %0, {%1, %1};" : "=l"(r) : "r"(__float_as_uint(x)));
    return r;
}
__device__ __forceinline__ float2 unpackf2(u64 v) {
    unsigned int lo, hi;
    asm("mov.b64 {%0, %1}, %2;" : "=r"(lo), "=r"(hi) : "l"(v));
    return make_float2(__uint_as_float(lo), __uint_as_float(hi));
}
#define FFMA2(acc, a, w) \
    asm("fma.rn.f32x2 %0, %1, %2, %0;" : "+l"(acc) : "l"(a), "l"(w))

// ---------------- GEMM tile, 256 threads, RPT rows/thread ----------------
// C[8*RPT][N] = act(A[8*RPT][K] @ Wg[K][N] + Bg[N])
// Thread (er=tid>>5, cc=tid&31): rows er*RPT..er*RPT+RPT-1.
// Cols: pair p -> (2cc+64p, 2cc+64p+1), p<P; scalar col 64P+cc if R==1.
// Wg staged through Wst (double-buffered, KC rows/chunk) with register
// prefetch of the next chunk; W smem reads software-pipelined by one k-pair.
// Preload sync covers A writes program-ordered before the call; no trailing
// sync (next gemm's preload sync, or an explicit one, covers the epilogue).
template<int K, int N, int KC, int AS, int CS, int P, int R, bool ACT, int RPT>
__device__ __forceinline__ void gemm_tile(const float* __restrict__ A,
                                          const float* __restrict__ Wg,
                                          const float* __restrict__ Bg,
                                          float* __restrict__ C,
                                          float* __restrict__ Wst)
{
    constexpr int NCHUNK = K / KC;
    constexpr int CHSZ = KC * N;
    constexpr int STG = (CHSZ + TPB - 1) / TPB;
    const int tid = threadIdx.x;
    const int er = tid >> 5;
    const int cc = tid & 31;

    u64 accp[RPT][P];
    float accs[RPT];
#pragma unroll
    for (int i = 0; i < RPT; i++) {
        accs[i] = 0.0f;
#pragma unroll
        for (int p = 0; p < P; p++) accp[i][p] = 0ULL;
    }

    // preload chunk 0 into buffer 0
    for (int idx = tid; idx < CHSZ; idx += TPB) Wst[idx] = Wg[idx];
    __syncthreads();

    for (int c = 0; c < NCHUNK; c++) {
        const float* buf = Wst + (c & 1) * CHSZ;
        float* nbuf = Wst + ((c + 1) & 1) * CHSZ;
        float tmp[STG];
        if (c + 1 < NCHUNK) {
            const float* src = Wg + (c + 1) * CHSZ;
#pragma unroll
            for (int t = 0; t < STG; t++) {
                int idx = tid + t * TPB;
                if (idx < CHSZ) tmp[t] = src[idx];
            }
        }
        const int k0 = c * KC;

        // register-pipelined W reads (one k-pair ahead)
        u64 w0[P], w1[P];
        float ws0 = 0.0f, ws1 = 0.0f;
#pragma unroll
        for (int p = 0; p < P; p++) {
            w0[p] = *(const u64*)(buf + 0 * N + 2 * cc + 64 * p);
            w1[p] = *(const u64*)(buf + 1 * N + 2 * cc + 64 * p);
        }
        if (R) { ws0 = buf[64 * P + cc]; ws1 = buf[N + 64 * P + cc]; }

#pragma unroll
        for (int kk = 0; kk < KC; kk += 2) {
            u64 nw0[P], nw1[P];
            float nws0 = 0.0f, nws1 = 0.0f;
            if (kk + 2 < KC) {
#pragma unroll
                for (int p = 0; p < P; p++) {
                    nw0[p] = *(const u64*)(buf + (kk + 2) * N + 2 * cc + 64 * p);
                    nw1[p] = *(const u64*)(buf + (kk + 3) * N + 2 * cc + 64 * p);
                }
                if (R) {
                    nws0 = buf[(kk + 2) * N + 64 * P + cc];
                    nws1 = buf[(kk + 3) * N + 64 * P + cc];
                }
            }
#pragma unroll
            for (int i = 0; i < RPT; i++) {
                float2 a2 = *(const float2*)(A + (er * RPT + i) * AS + k0 + kk);
                u64 a0 = packdup(a2.x);
                u64 a1 = packdup(a2.y);
#pragma unroll
                for (int p = 0; p < P; p++) {
                    FFMA2(accp[i][p], a0, w0[p]);
                    FFMA2(accp[i][p], a1, w1[p]);
                }
                if (R) accs[i] = fmaf(a2.y, ws1, fmaf(a2.x, ws0, accs[i]));
            }
#pragma unroll
            for (int p = 0; p < P; p++) { w0[p] = nw0[p]; w1[p] = nw1[p]; }
            if (R) { ws0 = nws0; ws1 = nws1; }
        }
        if (c + 1 < NCHUNK) {
#pragma unroll
            for (int t = 0; t < STG; t++) {
                int idx = tid + t * TPB;
                if (idx < CHSZ) nbuf[idx] = tmp[t];
            }
        }
        __syncthreads();
    }

    // epilogue: bias + activation + store
    float2 bv[P];
    float bs = 0.0f;
#pragma unroll
    for (int p = 0; p < P; p++) bv[p] = *(const float2*)(Bg + 2 * cc + 64 * p);
    if (R) bs = Bg[64 * P + cc];
#pragma unroll
    for (int i = 0; i < RPT; i++) {
#pragma unroll
        for (int p = 0; p < P; p++) {
            float2 v = unpackf2(accp[i][p]);
            v.x += bv[p].x;
            v.y += bv[p].y;
            if (ACT) { v.x = silu_f(v.x); v.y = silu_f(v.y); }
            *(float2*)(C + (er * RPT + i) * CS + 2 * cc + 64 * p) = v;
        }
        if (R) {
            float v = accs[i] + bs;
            if (ACT) v = silu_f(v);
            C[(er * RPT + i) * CS + 64 * P + cc] = v;
        }
    }
}

// ---------------- weight padding / prep (eW1 only) ----------------
__global__ void __launch_bounds__(256) pad_kernel(const float* __restrict__ eW1,
                                                  const float* __restrict__ eb1)
{
    const int A = NL * K1 * N1;
    const int B = NL * N1;
    int i = blockIdx.x * 256 + threadIdx.x;
    if (i < A) {
        int l = i / (K1 * N1);
        int r = (i / N1) % K1;
        int j = i % N1;
        g_eW1p[i] = (r < 130 && j < 260) ? eW1[(l * 130 + r) * 260 + j] : 0.0f;
    } else if (i < A + B) {
        int ii = i - A;
        int l = ii / N1, j = ii % N1;
        g_eb1p[ii] = (j < 260) ? eb1[l * 260 + j] : 0.0f;
    }
}

// ---------------- embed + pos copy ----------------
__global__ void __launch_bounds__(256) embed_kernel(const float* __restrict__ x,
                                                    const float* __restrict__ pos,
                                                    const float* __restrict__ W,
                                                    const float* __restrict__ b)
{
    int idx = blockIdx.x * 256 + threadIdx.x;
    if (idx < N_NODES * 3) g_coors[idx] = pos[idx];
    if (idx < N_NODES * HID) {
        int n = idx >> 6, j = idx & 63;
        float acc = b[j];
#pragma unroll
        for (int k = 0; k < F_IN; k++) acc = fmaf(x[n * F_IN + k], W[k * HID + j], acc);
        g_feats[idx] = acc;
    }
}

// ---------------- per-layer zero of aggregation buffers ----------------
__global__ void __launch_bounds__(256) zero_kernel()
{
    int i = blockIdx.x * 256 + threadIdx.x;
    if (i < N_NODES * HID) g_magg[i] = 0.0f;
    else if (i < N_NODES * HID + N_NODES * 3) g_cdelta[i - N_NODES * HID] = 0.0f;
}

// ---------------- per-node precompute: PA = feats@W1a + b1, PB = feats@W1b --
// smem: sF [0,4096), Wst [4096,8704)
#define PRE_SMEM_F 8704

__global__ void __launch_bounds__(256, 2) prenode_kernel(int l)
{
    extern __shared__ float sm[];
    float* sF = sm;
    float* Wst = sm + 4096;

    const int tid = threadIdx.x;
    const int n0 = blockIdx.x * 64;

    for (int idx = tid; idx < 64 * 64; idx += TPB) {
        int nl = idx >> 6, k = idx & 63;
        int n = n0 + nl;
        sF[idx] = (n < N_NODES) ? g_feats[n * HID + k] : 0.0f;
    }

    const float* W1 = g_eW1p + l * K1 * N1;
    gemm_tile<64, N1, 8, 64, N1, 4, 1, false, 8>(sF, W1, g_eb1p + l * N1,
                                                 g_PA + n0 * N1, Wst);
    gemm_tile<64, N1, 8, 64, N1, 4, 1, false, 8>(sF, W1 + 64 * N1, g_zbias,
                                                 g_PB + n0 * N1, Wst);
}

// ---------------- edge kernel (48 edges/block, 256 threads, 2 CTA/SM) -----
// smem float layout:
//   R1    [0, 13824)      : h1 (48x288) / c1 (48x264 padded stride)
//   mT    [13824, 16896)  : m (48x64)
//   Wst   [16896, 20992)  : double-buffered weight staging
//   sWea  [20992, 21280)  : eW1 row 128 (288)
//   sWdist[21280, 21568)  : eW1 row 129 (288)
//   srow  [21568, 21616)  : int
//   scol  [21616, 21664)  : int
//   srel  [21664, 21856)  : rx,ry,rz,dist per edge
//   sea   [21856, 21904)  : edge_attr
//   sdot  [21904, 22160)  : cW2 (256)
#define EDGE_SMEM_F 22160

__global__ void __launch_bounds__(256, 2) edge_kernel(const int* __restrict__ ei,
                                                      const float* __restrict__ eattr,
                                                      const float* __restrict__ eW2,
                                                      const float* __restrict__ eb2,
                                                      const float* __restrict__ cW1,
                                                      const float* __restrict__ cb1,
                                                      const float* __restrict__ cW2,
                                                      const float* __restrict__ cb2,
                                                      int l)
{
    extern __shared__ float sm[];
    float* R1 = sm;
    float* mT = sm + 13824;
    float* Wst = sm + 16896;
    float* sWea = sm + 20992;
    float* sWdist = sm + 21280;
    int* srow = (int*)(sm + 21568);
    int* scol = (int*)(sm + 21616);
    float* srel = sm + 21664;
    float* sea = sm + 21856;
    float* sdot = sm + 21904;

    const int tid = threadIdx.x;
    const int e0 = blockIdx.x * ETILE;

    // phase 0a: scalars + small weight vectors
    sdot[tid] = cW2[l * 256 + tid];
    {
        const float* Wea = g_eW1p + l * K1 * N1 + 128 * N1;
        for (int idx = tid; idx < 2 * N1; idx += TPB) {
            if (idx < N1) sWea[idx] = Wea[idx];
            else sWdist[idx - N1] = Wea[N1 + (idx - N1)];
        }
    }
    if (tid < ETILE) {
        int e = e0 + tid;
        int r = 0, c = 0;
        float ea = 0.0f;
        if (e < N_EDGES) {
            r = ei[e];
            c = ei[N_EDGES + e];
            ea = eattr[e];
        }
        srow[tid] = r;
        scol[tid] = c;
        float rx = g_coors[r * 3 + 0] - g_coors[c * 3 + 0];
        float ry = g_coors[r * 3 + 1] - g_coors[c * 3 + 1];
        float rz = g_coors[r * 3 + 2] - g_coors[c * 3 + 2];
        srel[tid * 4 + 0] = rx;
        srel[tid * 4 + 1] = ry;
        srel[tid * 4 + 2] = rz;
        srel[tid * 4 + 3] = rx * rx + ry * ry + rz * rz;
        sea[tid] = ea;
    }
    __syncthreads();

    // phase A: h1[e][:] = silu(PA[row] + PB[col] + ea*Wea + dist*Wdist)
    for (int idx = tid; idx < ETILE * 72; idx += TPB) {
        int e = idx / 72, q = idx - e * 72;
        float4 a = ((const float4*)(g_PA + srow[e] * N1))[q];
        float4 b = ((const float4*)(g_PB + scol[e] * N1))[q];
        float4 we = ((const float4*)sWea)[q];
        float4 wd = ((const float4*)sWdist)[q];
        float ea = sea[e], di = srel[e * 4 + 3];
        float4 v;
        v.x = silu_f(fmaf(di, wd.x, fmaf(ea, we.x, a.x + b.x)));
        v.y = silu_f(fmaf(di, wd.y, fmaf(ea, we.y, a.y + b.y)));
        v.z = silu_f(fmaf(di, wd.z, fmaf(ea, we.z, a.z + b.z)));
        v.w = silu_f(fmaf(di, wd.w, fmaf(ea, we.w, a.w + b.w)));
        ((float4*)(R1 + e * N1))[q] = v;
    }

    // GEMM2: m = silu(h1[:, :260] @ eW2 + eb2)   (preload sync covers phase A)
    gemm_tile<K2, 64, 20, N1, 64, 1, 0, true, 6>(R1, eW2 + l * K2 * HID,
                                                 eb2 + l * HID, mT, Wst);
    // GEMM3: c1 = silu(m @ cW1 + cb1), stride 264, written into R1
    gemm_tile<64, 256, 8, 64, 264, 4, 0, true, 6>(mT, cW1 + l * 64 * 256,
                                                  cb1 + l * 256, R1, Wst);
    __syncthreads();

    // dot: cw[e] = c1[e] . cW2 + cb2 (4 lanes per edge)
    if (tid < ETILE * 4) {
        int e = tid >> 2, q = tid & 3;
        float s = 0.0f;
#pragma unroll
        for (int t = 0; t < 64; t++)
            s = fmaf(R1[e * 264 + q + 4 * t], sdot[q + 4 * t], s);
        s += __shfl_xor_sync(0xFFFFFFFFu, s, 1);
        s += __shfl_xor_sync(0xFFFFFFFFu, s, 2);
        if (q == 0 && e0 + e < N_EDGES) {
            float cw = s + cb2[l];
            int r = srow[e];
            atomicAdd(&g_cdelta[r * 3 + 0], cw * srel[e * 4 + 0]);
            atomicAdd(&g_cdelta[r * 3 + 1], cw * srel[e * 4 + 1]);
            atomicAdd(&g_cdelta[r * 3 + 2], cw * srel[e * 4 + 2]);
        }
    }
    // scatter m into node aggregation
    for (int idx = tid; idx < ETILE * 64; idx += TPB) {
        int e = idx >> 6, k = idx & 63;
        if (e0 + e < N_EDGES)
            atomicAdd(&g_magg[srow[e] * HID + k], mT[e * 64 + k]);
    }
}

// ---------------- node kernel (64 nodes/block, 256 threads) ----------------
// smem: sH [0,8192), sT1 [8192,16384), Wst [16384,20480)
#define NODE_SMEM_F 20480

__global__ void __launch_bounds__(256, 2) node_kernel(const float* __restrict__ nW1,
                                                      const float* __restrict__ nb1,
                                                      const float* __restrict__ nW2,
                                                      const float* __restrict__ nb2,
                                                      int l)
{
    extern __shared__ float sm[];
    float* sH = sm;
    float* sT1 = sm + 8192;
    float* Wst = sm + 16384;

    const int tid = threadIdx.x;
    const int n0 = blockIdx.x * 64;

    for (int idx = tid; idx < 64 * 64; idx += TPB) {
        int nl = idx >> 6, k = idx & 63;
        int n = n0 + nl;
        float f = 0.0f, mg = 0.0f;
        if (n < N_NODES) { f = g_feats[n * HID + k]; mg = g_magg[n * HID + k]; }
        sH[nl * 128 + k] = f;
        sH[nl * 128 + 64 + k] = mg;
    }

    gemm_tile<128, 128, 16, 128, 128, 2, 0, true, 8>(sH, nW1 + l * 128 * 128,
                                                     nb1 + l * 128, sT1, Wst);
    gemm_tile<128, 64, 16, 128, 64, 1, 0, false, 8>(sT1, nW2 + l * 128 * 64,
                                                    nb2 + l * 64, sH, Wst);
    __syncthreads();

    for (int idx = tid; idx < 64 * 64; idx += TPB) {
        int nl = idx >> 6, k = idx & 63;
        int n = n0 + nl;
        if (n < N_NODES) g_feats[n * HID + k] += sH[nl * 64 + k];
    }
    if (tid < 192) {
        int n = n0 + tid / 3;
        int d = tid % 3;
        if (n < N_NODES) g_coors[n * 3 + d] += g_cdelta[n * 3 + d];
    }
}

// ---------------- final projection ----------------
__global__ void __launch_bounds__(256) final_kernel(const float* __restrict__ linW,
                                                    const float* __restrict__ linb,
                                                    float* __restrict__ out)
{
    int warp = (blockIdx.x * 256 + threadIdx.x) >> 5;
    int lane = threadIdx.x & 31;
    if (warp >= N_NODES) return;
    const float* f = g_feats + warp * HID;
    float s = fmaf(f[lane], linW[lane], f[lane + 32] * linW[lane + 32]);
#pragma unroll
    for (int o = 16; o > 0; o >>= 1) s += __shfl_xor_sync(0xFFFFFFFFu, s, o);
    if (lane == 0) out[warp] = s + linb[0];
}

// ---------------- launch ----------------
extern "C" void kernel_launch(void* const* d_in, const int* in_sizes, int n_in,
                              void* d_out, int out_size)
{
    const float* x      = (const float*)d_in[0];
    const float* pos    = (const float*)d_in[1];
    const int*   ei     = (const int*)  d_in[2];
    const float* eattr  = (const float*)d_in[3];
    const float* embedW = (const float*)d_in[4];
    const float* embedb = (const float*)d_in[5];
    const float* eW1    = (const float*)d_in[6];
    const float* eb1    = (const float*)d_in[7];
    const float* eW2    = (const float*)d_in[8];
    const float* eb2    = (const float*)d_in[9];
    const float* cW1    = (const float*)d_in[10];
    const float* cb1    = (const float*)d_in[11];
    const float* cW2    = (const float*)d_in[12];
    const float* cb2    = (const float*)d_in[13];
    const float* nW1    = (const float*)d_in[14];
    const float* nb1    = (const float*)d_in[15];
    const float* nW2    = (const float*)d_in[16];
    const float* nb2    = (const float*)d_in[17];
    const float* linW   = (const float*)d_in[18];
    const float* linb   = (const float*)d_in[19];
    float* out = (float*)d_out;

    cudaFuncSetAttribute(edge_kernel, cudaFuncAttributeMaxDynamicSharedMemorySize,
                         EDGE_SMEM_F * 4);
    cudaFuncSetAttribute(node_kernel, cudaFuncAttributeMaxDynamicSharedMemorySize,
                         NODE_SMEM_F * 4);
    cudaFuncSetAttribute(prenode_kernel, cudaFuncAttributeMaxDynamicSharedMemorySize,
                         PRE_SMEM_F * 4);

    {
        int total = NL * K1 * N1 + NL * N1;
        pad_kernel<<<(total + 255) / 256, 256>>>(eW1, eb1);
    }
    embed_kernel<<<(N_NODES * HID + 255) / 256, 256>>>(x, pos, embedW, embedb);

    const int egrid = (N_EDGES + ETILE - 1) / ETILE;
    const int ngrid = (N_NODES + 63) / 64;
    for (int l = 0; l < NL; l++) {
        prenode_kernel<<<ngrid, TPB, PRE_SMEM_F * 4>>>(l);
        int ztotal = N_NODES * HID + N_NODES * 3;
        zero_kernel<<<(ztotal + 255) / 256, 256>>>();
        edge_kernel<<<egrid, TPB, EDGE_SMEM_F * 4>>>(ei, eattr, eW2, eb2, cW1, cb1,
                                                     cW2, cb2, l);
        node_kernel<<<ngrid, TPB, NODE_SMEM_F * 4>>>(nW1, nb1, nW2, nb2, l);
    }
    final_kernel<<<(N_NODES * 32 + 255) / 256, 256>>>(linW, linb, out);
}